// round 16
// baseline (speedup 1.0000x reference)
#include <cuda_runtime.h>
#include <cuda_bf16.h>

// StyleGAN3 filtered activation, fully fused per-image:
//   up2x (12-tap separable FIR, polyphase) -> +bias, lrelu*sqrt(2), clamp(256)
//   -> down2x (12-tap separable FIR)
//
// One CTA per (n,c) image. All intermediates live in SMEM:
//   A_buf (19044 f): holds padded x first, then the 138x138 activated tensor
//   V_buf (8832  f): holds vertical-upsampled V[138][64], then D[64][138]
//
// Polyphase: intermediate rows 2m and 2m+1 share the same 6-tap input window
// (taps f[10-2s] / f[11-2s]); up gain 4 is folded as 2x into each 1D pass.

#define THREADS 256
#define HW      64
#define IM      138            // intermediate spatial size (2*64+10)
#define A_SIZE  (IM * IM)      // 19044
#define V_SIZE  (IM * HW)      // 8832
#define XPAD_R  74             // 64 rows + 5 zero rows each side
#define SMEM_FLOATS (A_SIZE + V_SIZE + 24)
#define SMEM_BYTES  (SMEM_FLOATS * 4)

__global__ void __launch_bounds__(THREADS, 2)
stylegan3_filtact_kernel(const float* __restrict__ x,
                         const float* __restrict__ bias,
                         const float* __restrict__ upf,
                         const float* __restrict__ downf,
                         float* __restrict__ out)
{
    extern __shared__ float sm[];
    float* Abuf = sm;                       // 19044 floats
    float* Vbuf = sm + A_SIZE;              // 8832 floats
    float* sce  = sm + A_SIZE + V_SIZE;     // 6  (even-phase up taps * 2)
    float* sco  = sce + 6;                  // 6  (odd-phase  up taps * 2)
    float* sgd  = sco + 6;                  // 12 (flipped down taps)

    const int tid = threadIdx.x;
    const int img = blockIdx.x;             // n*512 + c
    const int c   = img & 511;
    const float b = __ldg(&bias[c]);
    const float* gx   = x   + (size_t)img * (HW * HW);
    float*       gout = out + (size_t)img * (HW * HW);

    // ---- coefficients (polyphase split, gain 2 folded per up pass) ----
    if (tid < 6)            sce[tid]      = 2.0f * __ldg(&upf[10 - 2 * tid]);
    else if (tid < 12)      sco[tid - 6]  = 2.0f * __ldg(&upf[11 - 2 * (tid - 6)]);
    else if (tid < 24)      sgd[tid - 12] = __ldg(&downf[11 - (tid - 12)]);

    // ---- phase 1: load x into Abuf with 5-row zero pad top/bottom ----
    // padded row r corresponds to input row r-5
    for (int idx = tid; idx < XPAD_R * HW; idx += THREADS) {
        int r = idx >> 6;
        int w = idx & 63;
        float v = 0.0f;
        if (r >= 5 && r < 69) v = __ldg(&gx[(r - 5) * HW + w]);
        Abuf[idx] = v;
    }
    __syncthreads();

    float ce[6], co[6];
#pragma unroll
    for (int s = 0; s < 6; s++) { ce[s] = sce[s]; co[s] = sco[s]; }

    // ---- phase 2: vertical up  V[2m][w], V[2m+1][w] from shared window ----
    for (int t = tid; t < 69 * HW; t += THREADS) {
        int ip = t >> 6;           // pair index 0..68  (rows 2ip, 2ip+1)
        int w  = t & 63;
        const float* xp = &Abuf[ip * HW + w];   // padded row ip == x row ip-5
        float ve = 0.0f, vo = 0.0f;
#pragma unroll
        for (int s = 0; s < 6; s++) {
            float xv = xp[s * HW];
            ve = fmaf(ce[s], xv, ve);
            vo = fmaf(co[s], xv, vo);
        }
        Vbuf[(2 * ip) * HW + w]     = ve;
        Vbuf[(2 * ip + 1) * HW + w] = vo;
    }
    __syncthreads();

    // ---- phase 3: horizontal up + bias + lrelu*sqrt2 + clamp -> A[138][138]
    const float SQ2  = 1.41421356237309515f;
    const float NSQ2 = 0.2f * 1.41421356237309515f;
    for (int t = tid; t < IM * 69; t += THREADS) {
        int i  = t / 69;
        int kp = t - i * 69;        // column pair 0..68 (cols 2kp, 2kp+1)
        int j0 = kp - 5;
        const float* vr = &Vbuf[i * HW];
        float ue = 0.0f, uo = 0.0f;
#pragma unroll
        for (int s = 0; s < 6; s++) {
            int j = j0 + s;
            float vv = (j >= 0 && j < HW) ? vr[j] : 0.0f;
            ue = fmaf(ce[s], vv, ue);
            uo = fmaf(co[s], vv, uo);
        }
        float ae = ue + b, ao = uo + b;
        ae = (ae >= 0.0f) ? ae * SQ2 : ae * NSQ2;
        ao = (ao >= 0.0f) ? ao * SQ2 : ao * NSQ2;
        ae = fminf(fmaxf(ae, -256.0f), 256.0f);
        ao = fminf(fmaxf(ao, -256.0f), 256.0f);
        float2 pr = make_float2(ae, ao);
        *reinterpret_cast<float2*>(&Abuf[i * IM + 2 * kp]) = pr;
    }
    __syncthreads();

    float gd[12];
#pragma unroll
    for (int s = 0; s < 12; s++) gd[s] = sgd[s];

    // ---- phase 4: vertical down  D[o][k] = sum_t gd[t]*A[2o+t][k] ----
    // 4 outputs per thread down a column (rolling window: 18 loads / 4 outs)
    for (int t = tid; t < 16 * IM; t += THREADS) {
        int oq = t / IM;
        int k  = t - oq * IM;
        const float* ap = &Abuf[(8 * oq) * IM + k];
        float a0 = 0.0f, a1 = 0.0f, a2 = 0.0f, a3 = 0.0f;
#pragma unroll
        for (int r = 0; r < 18; r++) {
            float a = ap[r * IM];
            if (r < 12)            a0 = fmaf(gd[r],     a, a0);
            if (r >= 2 && r < 14)  a1 = fmaf(gd[r - 2], a, a1);
            if (r >= 4 && r < 16)  a2 = fmaf(gd[r - 4], a, a2);
            if (r >= 6)            a3 = fmaf(gd[r - 6], a, a3);
        }
        Vbuf[(4 * oq + 0) * IM + k] = a0;
        Vbuf[(4 * oq + 1) * IM + k] = a1;
        Vbuf[(4 * oq + 2) * IM + k] = a2;
        Vbuf[(4 * oq + 3) * IM + k] = a3;
    }
    __syncthreads();

    // ---- phase 5: horizontal down -> out[o][p], float4 coalesced stores ----
    for (int t = tid; t < 64 * 16; t += THREADS) {
        int o  = t >> 4;
        int pq = t & 15;                 // 4 outputs p = 4*pq .. 4*pq+3
        const float* dp = &Vbuf[o * IM + 8 * pq];
        float a0 = 0.0f, a1 = 0.0f, a2 = 0.0f, a3 = 0.0f;
#pragma unroll
        for (int r = 0; r < 18; r++) {
            float d = dp[r];
            if (r < 12)            a0 = fmaf(gd[r],     d, a0);
            if (r >= 2 && r < 14)  a1 = fmaf(gd[r - 2], d, a1);
            if (r >= 4 && r < 16)  a2 = fmaf(gd[r - 4], d, a2);
            if (r >= 6)            a3 = fmaf(gd[r - 6], d, a3);
        }
        float4 v = make_float4(a0, a1, a2, a3);
        *reinterpret_cast<float4*>(&gout[o * HW + 4 * pq]) = v;
    }
}

extern "C" void kernel_launch(void* const* d_in, const int* in_sizes, int n_in,
                              void* d_out, int out_size)
{
    const float* x     = (const float*)d_in[0];
    const float* bias  = (const float*)d_in[1];
    const float* upf   = (const float*)d_in[2];
    const float* downf = (const float*)d_in[3];
    float* out = (float*)d_out;

    cudaFuncSetAttribute(stylegan3_filtact_kernel,
                         cudaFuncAttributeMaxDynamicSharedMemorySize, SMEM_BYTES);

    stylegan3_filtact_kernel<<<8 * 512, THREADS, SMEM_BYTES>>>(x, bias, upf, downf, out);
}

// round 17
// speedup vs baseline: 1.3127x; 1.3127x over previous
#include <cuda_runtime.h>
#include <cuda_bf16.h>

// StyleGAN3 filtered activation, fused, 4 CTAs per (n,c) image.
// CTA q computes output rows [16q, 16q+16). All intermediates in SMEM:
//   Act[42][138]  activated up-sampled tile (rows 32q .. 32q+41)
//   Vp [42][74]   vertically-upsampled tile, zero-padded 5 cols each side
//   Xp [26][64]   padded input rows (aliased over Act, dead before Act writes)
//   D  [16][138]  vertical-downsample result (aliased over Vp)
// Polyphase up: rows/cols 2m,2m+1 share one 6-tap window
// (ce[s]=2*f[10-2s], co[s]=2*f[11-2s]); down taps gd[r]=f[11-r].

#define THREADS 256
#define HW      64
#define IMW     138
#define AROWS   42
#define VW      74
#define XROWS   26
#define ACT_SIZE (AROWS * IMW)          // 5796
#define VP_OFF   ACT_SIZE
#define VP_SIZE  (AROWS * VW)           // 3108
#define CONST_OFF (VP_OFF + VP_SIZE)    // 8904
#define SMEM_FLOATS (CONST_OFF + 24)
#define SMEM_BYTES  (SMEM_FLOATS * 4)   // 35712

__global__ void __launch_bounds__(THREADS, 6)
stylegan3_filtact_kernel(const float* __restrict__ x,
                         const float* __restrict__ bias,
                         const float* __restrict__ upf,
                         const float* __restrict__ downf,
                         float* __restrict__ out)
{
    extern __shared__ float sm[];
    float* Act = sm;                 // phase 3 write, phase 4 read
    float* Xp  = sm;                 // alias: phase 1 write, phase 2 read
    float* Vp  = sm + VP_OFF;        // phase 2 write, phase 3 read
    float* Dd  = sm + VP_OFF;        // alias: phase 4 write, phase 5 read
    float* sce = sm + CONST_OFF;
    float* sco = sce + 6;
    float* sgd = sco + 6;

    const int tid = threadIdx.x;
    const int bx  = blockIdx.x;
    const int img = bx >> 2;
    const int q   = bx & 3;
    const int c   = img & 511;
    const int ip0 = 16 * q;          // first V row-pair index
    const int o0  = 16 * q;          // first output row
    const float b = __ldg(&bias[c]);
    const float* gx   = x   + (size_t)img * (HW * HW);
    float*       gout = out + (size_t)img * (HW * HW);

    // ---- coefficients ----
    if (tid < 6)        sce[tid]      = 2.0f * __ldg(&upf[10 - 2 * tid]);
    else if (tid < 12)  sco[tid - 6]  = 2.0f * __ldg(&upf[11 - 2 * (tid - 6)]);
    else if (tid < 24)  sgd[tid - 12] = __ldg(&downf[11 - (tid - 12)]);

    // ---- phase 1: load x rows [ip0-5, ip0+20] into Xp (zero outside) ----
    for (int idx = tid; idx < XROWS * HW; idx += THREADS) {
        int rl = idx >> 6;
        int w  = idx & 63;
        int xr = ip0 - 5 + rl;
        Xp[idx] = (xr >= 0 && xr < HW) ? __ldg(&gx[xr * HW + w]) : 0.0f;
    }
    // zero Vp pad columns (5 left, 5 right per row)
    for (int idx = tid; idx < AROWS * 10; idx += THREADS) {
        int r  = idx / 10;
        int cp = idx - 10 * r;
        int col = (cp < 5) ? cp : (64 + cp);   // 0..4 and 69..73
        Vp[r * VW + col] = 0.0f;
    }
    __syncthreads();

    float ce[6], co[6];
#pragma unroll
    for (int s = 0; s < 6; s++) { ce[s] = sce[s]; co[s] = sco[s]; }

    // ---- phase 2: vertical up -> Vp rows 0..41 (21 pairs), cols 5..68 ----
    for (int idx = tid; idx < 21 * HW; idx += THREADS) {
        int ipl = idx >> 6;
        int w   = idx & 63;
        const float* xp = &Xp[ipl * HW + w];
        float ve = 0.0f, vo = 0.0f;
#pragma unroll
        for (int s = 0; s < 6; s++) {
            float xv = xp[s * HW];
            ve = fmaf(ce[s], xv, ve);
            vo = fmaf(co[s], xv, vo);
        }
        Vp[(2 * ipl)     * VW + 5 + w] = ve;
        Vp[(2 * ipl + 1) * VW + 5 + w] = vo;
    }
    __syncthreads();

    // ---- phase 3: horizontal up + bias + lrelu*sqrt2 + clamp -> Act ----
    const float SQ2  = 1.41421356237309515f;
    const float NSQ2 = 0.2f * 1.41421356237309515f;
    {
        int i  = tid / 69;
        int kp = tid - 69 * i;
        while (i < AROWS) {
            const float* vr = &Vp[i * VW + kp];   // j=kp-5+s lives at vr[s]
            float ue = b, uo = b;
#pragma unroll
            for (int s = 0; s < 6; s++) {
                float vv = vr[s];
                ue = fmaf(ce[s], vv, ue);
                uo = fmaf(co[s], vv, uo);
            }
            float ae = (ue >= 0.0f) ? ue * SQ2 : ue * NSQ2;
            float ao = (uo >= 0.0f) ? uo * SQ2 : uo * NSQ2;
            ae = fminf(fmaxf(ae, -256.0f), 256.0f);
            ao = fminf(fmaxf(ao, -256.0f), 256.0f);
            *reinterpret_cast<float2*>(&Act[i * IMW + 2 * kp]) = make_float2(ae, ao);
            kp += 49; i += 3;                       // += 256 items
            if (kp >= 69) { kp -= 69; ++i; }
        }
    }
    __syncthreads();

    float gd[12];
#pragma unroll
    for (int s = 0; s < 12; s++) gd[s] = sgd[s];

    // ---- phase 4: vertical down: D[4oq+d][k] from Act rows 8oq+r ----
    {
        int oq = tid / 138;
        int k  = tid - 138 * oq;
        while (oq < 4) {
            const float* ap = &Act[(8 * oq) * IMW + k];
            float a0 = 0.0f, a1 = 0.0f, a2 = 0.0f, a3 = 0.0f;
#pragma unroll
            for (int r = 0; r < 18; r++) {
                float a = ap[r * IMW];
                if (r < 12)            a0 = fmaf(gd[r],     a, a0);
                if (r >= 2 && r < 14)  a1 = fmaf(gd[r - 2], a, a1);
                if (r >= 4 && r < 16)  a2 = fmaf(gd[r - 4], a, a2);
                if (r >= 6)            a3 = fmaf(gd[r - 6], a, a3);
            }
            Dd[(4 * oq + 0) * IMW + k] = a0;
            Dd[(4 * oq + 1) * IMW + k] = a1;
            Dd[(4 * oq + 2) * IMW + k] = a2;
            Dd[(4 * oq + 3) * IMW + k] = a3;
            k += 118; ++oq;                         // += 256 items
            if (k >= 138) { k -= 138; ++oq; }
        }
    }
    __syncthreads();

    // ---- phase 5: horizontal down, exactly 1 item/thread, float4 stores ----
    {
        int ol = tid >> 4;           // 0..15
        int pq = tid & 15;           // output cols 4pq..4pq+3
        const float* dp = &Dd[ol * IMW + 8 * pq];
        float a0 = 0.0f, a1 = 0.0f, a2 = 0.0f, a3 = 0.0f;
#pragma unroll
        for (int r = 0; r < 18; r++) {
            float d = dp[r];
            if (r < 12)            a0 = fmaf(gd[r],     d, a0);
            if (r >= 2 && r < 14)  a1 = fmaf(gd[r - 2], d, a1);
            if (r >= 4 && r < 16)  a2 = fmaf(gd[r - 4], d, a2);
            if (r >= 6)            a3 = fmaf(gd[r - 6], d, a3);
        }
        *reinterpret_cast<float4*>(&gout[(o0 + ol) * HW + 4 * pq]) =
            make_float4(a0, a1, a2, a3);
    }
}

extern "C" void kernel_launch(void* const* d_in, const int* in_sizes, int n_in,
                              void* d_out, int out_size)
{
    const float* x     = (const float*)d_in[0];
    const float* bias  = (const float*)d_in[1];
    const float* upf   = (const float*)d_in[2];
    const float* downf = (const float*)d_in[3];
    float* out = (float*)d_out;

    cudaFuncSetAttribute(stylegan3_filtact_kernel,
                         cudaFuncAttributeMaxDynamicSharedMemorySize, SMEM_BYTES);

    stylegan3_filtact_kernel<<<8 * 512 * 4, THREADS, SMEM_BYTES>>>(x, bias, upf, downf, out);
}